// round 7
// baseline (speedup 1.0000x reference)
#include <cuda_runtime.h>
#include <cuda_bf16.h>
#include <cstdint>

#define Bsz 256
#define Ssz 256
#define Esz 256
#define Hsz 1024
#define G4  4096   // 4*H

// ---- step kernel tiling: 8 warps (2x4), warp tile M32xN32 ----
#define BMt 64                  // M tile (batch rows per CTA)
#define HT  32                  // h columns per gate per CTA
#define NT  128                 // N tile = 4 gates * HT (gate-interleaved)
#define KC  64                  // K chunk (bf16 elements = 128 B row)
#define NCHUNK (Hsz / KC)       // 16
#define NSTAGE 4

// ---- smem layout ----
#define A_MAT_BYTES (BMt * KC * 2)                      // 8 KB per matrix
#define B_MAT_BYTES (NT * KC * 2)                       // 16 KB per matrix
#define STAGE_BYTES (2 * A_MAT_BYTES + 2 * B_MAT_BYTES) // 48 KB
#define OFF_AHI 0
#define OFF_ALO (A_MAT_BYTES)
#define OFF_BHI (2 * A_MAT_BYTES)
#define OFF_BLO (2 * A_MAT_BYTES + B_MAT_BYTES)
#define SMEM_TOTAL (NSTAGE * STAGE_BYTES)               // 192 KB

// ---- device globals (no allocation allowed) ----
// proj tables gate-packed: [tok][h][gate] so one float4 = all 4 gates
__device__ float g_letter_proj[30 * G4];
__device__ float g_state_proj[4 * G4];
__device__ __nv_bfloat16 g_W_hi[(size_t)G4 * Hsz];   // 8 MB
__device__ __nv_bfloat16 g_W_lo[(size_t)G4 * Hsz];   // 8 MB
__device__ __nv_bfloat16 g_h_hi[2][Bsz * Hsz];
__device__ __nv_bfloat16 g_h_lo[2][Bsz * Hsz];
__device__ float g_c[2][Bsz * Hsz];

// ---------------------------------------------------------------------------
// PTX helpers
// ---------------------------------------------------------------------------
__device__ __forceinline__ uint32_t smem_u32(const void* p) {
    uint32_t a;
    asm("{ .reg .u64 t; cvta.to.shared.u64 t, %1; cvt.u32.u64 %0, t; }"
        : "=r"(a) : "l"(p));
    return a;
}
__device__ __forceinline__ void cp16(uint32_t s, const void* g) {
    asm volatile("cp.async.cg.shared.global [%0], [%1], 16;"
                 :: "r"(s), "l"(g) : "memory");
}
#define CP_COMMIT() asm volatile("cp.async.commit_group;" ::: "memory")
#define CP_WAIT2()  asm volatile("cp.async.wait_group 2;" ::: "memory")

__device__ __forceinline__ void ldsm4(uint32_t a, uint32_t* r) {
    asm volatile("ldmatrix.sync.aligned.m8n8.x4.shared.b16 {%0,%1,%2,%3}, [%4];"
                 : "=r"(r[0]), "=r"(r[1]), "=r"(r[2]), "=r"(r[3]) : "r"(a));
}
__device__ __forceinline__ void mma16816(float* c, const uint32_t* a,
                                         const uint32_t* b) {
    asm volatile(
        "mma.sync.aligned.m16n8k16.row.col.f32.bf16.bf16.f32 "
        "{%0,%1,%2,%3}, {%4,%5,%6,%7}, {%8,%9}, {%0,%1,%2,%3};"
        : "+f"(c[0]), "+f"(c[1]), "+f"(c[2]), "+f"(c[3])
        : "r"(a[0]), "r"(a[1]), "r"(a[2]), "r"(a[3]), "r"(b[0]), "r"(b[1]));
}
__device__ __forceinline__ void stcs(float* p, float v) {
    asm volatile("st.global.cs.f32 [%0], %1;" :: "l"(p), "f"(v) : "memory");
}
__device__ __forceinline__ float sigmoidf_(float x) {
    return 1.0f / (1.0f + expf(-x));
}

// ---------------------------------------------------------------------------
// One-time prep: split W_hh into bf16 hi/lo
// ---------------------------------------------------------------------------
__global__ void wsplit_kernel(const float* __restrict__ W) {
    size_t i = ((size_t)blockIdx.x * blockDim.x + threadIdx.x) * 4;
    float4 w = *(const float4*)(W + i);
    float v[4] = {w.x, w.y, w.z, w.w};
    #pragma unroll
    for (int j = 0; j < 4; j++) {
        __nv_bfloat16 hi = __float2bfloat16(v[j]);
        g_W_hi[i + j] = hi;
        g_W_lo[i + j] = __float2bfloat16(v[j] - __bfloat162float(hi));
    }
}

// ---------------------------------------------------------------------------
// One-time prep: x_proj tables, gate-packed layout [tok][h][gate]
// ---------------------------------------------------------------------------
__global__ void proj_kernel(const float* __restrict__ letter_emb,
                            const float* __restrict__ state_emb,
                            const float* __restrict__ W_ih,
                            const float* __restrict__ b_ih,
                            const float* __restrict__ b_hh) {
    int tok  = blockIdx.y;
    int g    = blockIdx.x * 8 + (threadIdx.x >> 5);   // PyTorch row: gate*H + h
    int lane = threadIdx.x & 31;

    const float* emb;
    const float* w;
    if (tok < 30) {
        emb = letter_emb + tok * Esz;
        w   = W_ih + (size_t)g * (2 * Esz);
    } else {
        emb = state_emb + (tok - 30) * Esz;
        w   = W_ih + (size_t)g * (2 * Esz) + Esz;
    }

    float acc = 0.f;
    for (int k = lane; k < Esz; k += 32)
        acc += emb[k] * w[k];
    #pragma unroll
    for (int off = 16; off; off >>= 1)
        acc += __shfl_xor_sync(0xFFFFFFFFu, acc, off);

    if (lane == 0) {
        int gate = g >> 10;
        int h    = g & 1023;
        int idx  = h * 4 + gate;       // gate-packed
        if (tok < 30)
            g_letter_proj[tok * G4 + idx] = acc + b_ih[g] + b_hh[g];
        else
            g_state_proj[(tok - 30) * G4 + idx] = acc;
    }
}

// ---------------------------------------------------------------------------
// HMMA LSTM step. grid (32, 4) = 128 CTAs, 256 threads (8 warps, 2x4).
// B smem row n: gate = n&3, hcol = n>>2 (gate-interleaved) -> register epilogue.
// D = Ahi*Bhi + Alo*Bhi + Ahi*Blo (fp32 accum). 4-stage cp.async pipeline,
// fragment-level software pipelining across ks.
// ---------------------------------------------------------------------------
__global__ void __launch_bounds__(256, 1)
lstm_step_mma(const int* __restrict__ letter_seq,
              const int* __restrict__ state_seq,
              float* __restrict__ out_h,
              float* __restrict__ out_c,
              int s) {
    extern __shared__ char smem[];
    const uint32_t smem_base = smem_u32(smem);

    const int tid = threadIdx.x;
    const int h0  = blockIdx.x * HT;
    const int bm0 = blockIdx.y * BMt;
    const int rbuf = (s & 1) ^ 1;
    const int wbuf = s & 1;

    const int wid = tid >> 5;
    const int l   = tid & 31;
    const int wm  = wid >> 2;         // 0..1
    const int wn  = wid & 3;          // 0..3

    // ---- epilogue cell mapping (register epilogue, no D smem) ----
    // per (mf, nf): row = wm*32 + mf*16 + (l>>2) + 8*(l&1)
    //               hcol = wn*8 + nf*2 + ((l>>1)&1)
    const int row0 = wm * 32 + (l >> 2) + 8 * (l & 1);
    const int hc_b = wn * 8 + ((l >> 1) & 1);

    // ---- prefetch epilogue scalars (independent of the GEMM) ----
    int lt[2], st[2];
    float cprev[2][4];
    #pragma unroll
    for (int mf = 0; mf < 2; mf++) {
        const int b = bm0 + row0 + mf * 16;
        lt[mf] = letter_seq[b * Ssz + s];
        st[mf] = state_seq[b * Ssz + s];
        #pragma unroll
        for (int nf = 0; nf < 4; nf++)
            cprev[mf][nf] = (s > 0)
                ? g_c[rbuf][(size_t)b * Hsz + h0 + hc_b + nf * 2] : 0.f;
    }

    float acc[2][4][4];
    #pragma unroll
    for (int i = 0; i < 2; i++)
        #pragma unroll
        for (int j = 0; j < 4; j++)
            #pragma unroll
            for (int k = 0; k < 4; k++)
                acc[i][j][k] = 0.f;

    if (s > 0) {
        // ---- stage-load constants ----
        const int r  = tid >> 3;                 // 0..31
        const int gq = tid & 7;                  // 16B granule in 128B row
        const uint32_t sw = (uint32_t)((gq ^ (r & 7)) * 16);
        const __nv_bfloat16* hh = g_h_hi[rbuf] + (size_t)(bm0 + r) * Hsz + gq * 8;
        const __nv_bfloat16* hl = g_h_lo[rbuf] + (size_t)(bm0 + r) * Hsz + gq * 8;
        // gate-interleaved B rows: n = j*32 + r -> gate n&3, hcol n>>2
        size_t woff[4];
        #pragma unroll
        for (int j = 0; j < 4; j++) {
            int n = j * 32 + r;
            woff[j] = ((size_t)(n & 3) * Hsz + h0 + (n >> 2)) * Hsz + gq * 8;
        }

        auto load_stage = [&](int ch) {
            const int k0 = ch * KC;
            const uint32_t sb = smem_base + (uint32_t)(ch & (NSTAGE - 1)) * STAGE_BYTES;
            cp16(sb + OFF_AHI + r * 128 + sw,        hh + k0);
            cp16(sb + OFF_AHI + (r + 32) * 128 + sw, hh + k0 + 32 * Hsz);
            cp16(sb + OFF_ALO + r * 128 + sw,        hl + k0);
            cp16(sb + OFF_ALO + (r + 32) * 128 + sw, hl + k0 + 32 * Hsz);
            #pragma unroll
            for (int j = 0; j < 4; j++) {
                const uint32_t sn = (uint32_t)(j * 32 + r) * 128 + sw;
                cp16(sb + OFF_BHI + sn, g_W_hi + woff[j] + k0);
                cp16(sb + OFF_BLO + sn, g_W_lo + woff[j] + k0);
            }
        };

        // ---- ldmatrix lane constants ----
        const int a_r0 = wm * 32 + (l & 7) + ((l >> 3) & 1) * 8;
        const int a_kh = l >> 4;
        const int b_n0 = wn * 32 + (l & 7) + (l >> 4) * 8;
        const int b_kh = (l >> 3) & 1;

        // fragment double buffers
        uint32_t ah[2][2][4], al[2][2][4], bh[2][2][4], bl[2][2][4];

        auto ldfrag = [&](int fb, uint32_t sb, int ks) {
            const int agq = ks * 2 + a_kh;
            const int bgq = ks * 2 + b_kh;
            #pragma unroll
            for (int mf = 0; mf < 2; mf++) {
                int ar = a_r0 + mf * 16;
                uint32_t arow = (uint32_t)ar * 128
                              + (uint32_t)((agq ^ (ar & 7)) * 16);
                ldsm4(sb + OFF_AHI + arow, ah[fb][mf]);
                ldsm4(sb + OFF_ALO + arow, al[fb][mf]);
            }
            #pragma unroll
            for (int x = 0; x < 2; x++) {
                int bn = b_n0 + x * 16;
                uint32_t brow = (uint32_t)bn * 128
                              + (uint32_t)((bgq ^ (bn & 7)) * 16);
                ldsm4(sb + OFF_BHI + brow, bh[fb][x]);
                ldsm4(sb + OFF_BLO + brow, bl[fb][x]);
            }
        };
        auto mma_all = [&](int fb) {
            #pragma unroll
            for (int mf = 0; mf < 2; mf++)
                #pragma unroll
                for (int x = 0; x < 2; x++) {
                    mma16816(acc[mf][x * 2],     ah[fb][mf], &bh[fb][x][0]);
                    mma16816(acc[mf][x * 2 + 1], ah[fb][mf], &bh[fb][x][2]);
                }
            #pragma unroll
            for (int mf = 0; mf < 2; mf++)
                #pragma unroll
                for (int x = 0; x < 2; x++) {
                    mma16816(acc[mf][x * 2],     al[fb][mf], &bh[fb][x][0]);
                    mma16816(acc[mf][x * 2 + 1], al[fb][mf], &bh[fb][x][2]);
                }
            #pragma unroll
            for (int mf = 0; mf < 2; mf++)
                #pragma unroll
                for (int x = 0; x < 2; x++) {
                    mma16816(acc[mf][x * 2],     ah[fb][mf], &bl[fb][x][0]);
                    mma16816(acc[mf][x * 2 + 1], ah[fb][mf], &bl[fb][x][2]);
                }
        };

        load_stage(0); CP_COMMIT();
        load_stage(1); CP_COMMIT();
        load_stage(2); CP_COMMIT();

        for (int ch = 0; ch < NCHUNK; ch++) {
            CP_WAIT2();
            __syncthreads();
            if (ch + 3 < NCHUNK) load_stage(ch + 3);
            CP_COMMIT();

            const uint32_t sb = smem_base
                              + (uint32_t)(ch & (NSTAGE - 1)) * STAGE_BYTES;
            ldfrag(0, sb, 0);
            #pragma unroll
            for (int ks = 0; ks < 4; ks++) {
                if (ks < 3) ldfrag((ks + 1) & 1, sb, ks + 1);
                mma_all(ks & 1);
            }
        }
    }

    // ---- register epilogue: shfl gate exchange + fused LSTM cell ----
    {
        const size_t sbase = (size_t)s * Hsz;
        #pragma unroll
        for (int mf = 0; mf < 2; mf++) {
            const int b = bm0 + row0 + mf * 16;
            const float* lp = g_letter_proj + (size_t)lt[mf] * G4;
            const float* sp = g_state_proj  + (size_t)st[mf] * G4;
            #pragma unroll
            for (int nf = 0; nf < 4; nf++) {
                float* c = acc[mf][nf];
                // lanes l (gates 0,1) / l^1 (gates 2,3) swap row-halves
                float sA = (l & 1) ? c[0] : c[2];
                float sB = (l & 1) ? c[1] : c[3];
                float rA = __shfl_xor_sync(0xFFFFFFFFu, sA, 1);
                float rB = __shfl_xor_sync(0xFFFFFFFFu, sB, 1);
                float gi, gf, gg, go;
                if ((l & 1) == 0) { gi = c[0]; gf = c[1]; gg = rA; go = rB; }
                else              { gi = rA;  gf = rB;  gg = c[2]; go = c[3]; }

                const int habs = h0 + hc_b + nf * 2;
                float4 lp4 = *(const float4*)(lp + habs * 4);
                float4 sp4 = *(const float4*)(sp + habs * 4);
                float pi = gi + lp4.x + sp4.x;
                float pf = gf + lp4.y + sp4.y;
                float pg = gg + lp4.z + sp4.z;
                float po = go + lp4.w + sp4.w;

                float cc = sigmoidf_(pf) * cprev[mf][nf]
                         + sigmoidf_(pi) * tanhf(pg);
                float hv = sigmoidf_(po) * tanhf(cc);

                const size_t obase = (size_t)b * (Ssz * Hsz) + sbase + habs;
                stcs(out_h + obase, hv);
                stcs(out_c + obase, cc);
                const size_t cb = (size_t)b * Hsz + habs;
                g_c[wbuf][cb] = cc;
                __nv_bfloat16 hb = __float2bfloat16(hv);
                g_h_hi[wbuf][cb] = hb;
                g_h_lo[wbuf][cb] = __float2bfloat16(hv - __bfloat162float(hb));
            }
        }
    }
}

// ---------------------------------------------------------------------------
extern "C" void kernel_launch(void* const* d_in, const int* in_sizes, int n_in,
                              void* d_out, int out_size) {
    const int*   letter_seq = (const int*)d_in[0];
    const int*   state_seq  = (const int*)d_in[1];
    const float* letter_emb = (const float*)d_in[2];
    const float* state_emb  = (const float*)d_in[3];
    const float* W_ih       = (const float*)d_in[4];
    const float* W_hh       = (const float*)d_in[5];
    const float* b_ih       = (const float*)d_in[6];
    const float* b_hh       = (const float*)d_in[7];

    float* out_h = (float*)d_out;
    float* out_c = out_h + (size_t)Bsz * Ssz * Hsz;

    static int smem_set = 0;
    if (!smem_set) {
        cudaFuncSetAttribute(lstm_step_mma,
                             cudaFuncAttributeMaxDynamicSharedMemorySize,
                             SMEM_TOTAL);
        smem_set = 1;
    }

    wsplit_kernel<<<(G4 * Hsz) / (256 * 4), 256>>>(W_hh);
    proj_kernel<<<dim3(G4 / 8, 34), 256>>>(letter_emb, state_emb, W_ih, b_ih, b_hh);

    for (int s = 0; s < Ssz; s++) {
        lstm_step_mma<<<dim3(Hsz / HT, Bsz / BMt), 256, SMEM_TOTAL>>>(
            letter_seq, state_seq, out_h, out_c, s);
    }
}